// round 5
// baseline (speedup 1.0000x reference)
#include <cuda_runtime.h>
#include <math.h>
#include <stdint.h>

#define TT 2048
#define DD 1024
#define HH 2048
#define EE 8

#define BM 128
#define BN 128
#define BK 32
#define NTHREADS 128
#define STAGES 3

// SMEM word layout per stage: A [128][36], B [32][136]
#define A_STRIDE 36
#define B_STRIDE 136
#define A_BUF_W (BM * A_STRIDE)            // 4608 words (18432 B)
#define B_BUF_W (BK * B_STRIDE)            // 4352 words (17408 B)
#define A_BUF_B (A_BUF_W * 4)
#define B_BUF_B (B_BUF_W * 4)
#define SMEM_DYN (STAGES * (A_BUF_B + B_BUF_B))   // 107520 B

// -------- device scratch (no runtime allocation allowed) --------
__device__ int   g_count[EE];
__device__ int   g_offset[EE];
__device__ int   g_tok[EE * TT];
__device__ int   g_se[2 * TT];
__device__ int   g_sp[2 * TT];
__device__ float g_wt2[2 * TT];
__device__ __align__(16) float g_x[(size_t)TT * DD];                 // tf32-rounded x
__device__ __align__(16) float g_h[(size_t)(2 * TT + BM) * HH];      // gelu out (tf32-rounded)
__device__ __align__(16) float g_y[(size_t)(2 * TT) * DD];           // per-slot ffn2 out

// ---------------- helpers ----------------
__device__ __forceinline__ uint32_t smem_u32(const void* p) {
    uint32_t a;
    asm("{ .reg .u64 t; cvta.to.shared.u64 t, %1; cvt.u32.u64 %0, t; }" : "=r"(a) : "l"(p));
    return a;
}
__device__ __forceinline__ uint32_t f2tf(float f) {
    uint32_t r;
    asm("cvt.rna.tf32.f32 %0, %1;" : "=r"(r) : "f"(f));
    return r;
}
__device__ __forceinline__ uint32_t f2tf_u(uint32_t raw) {
    return f2tf(__uint_as_float(raw));
}
#define CP_ASYNC16(dst, src) \
    asm volatile("cp.async.cg.shared.global [%0], [%1], 16;" :: "r"(dst), "l"(src) : "memory")
#define CP_COMMIT()  asm volatile("cp.async.commit_group;" ::: "memory")
#define CP_WAIT(n)   asm volatile("cp.async.wait_group %0;" :: "n"(n) : "memory")

__device__ __forceinline__ void ldsm4(uint32_t* r, uint32_t addr) {
    asm volatile("ldmatrix.sync.aligned.m8n8.x4.shared.b16 {%0,%1,%2,%3}, [%4];"
        : "=r"(r[0]), "=r"(r[1]), "=r"(r[2]), "=r"(r[3]) : "r"(addr));
}

__device__ __forceinline__ void mma_tf32(float* c, const uint32_t* a, const uint32_t* b) {
    asm volatile(
        "mma.sync.aligned.m16n8k8.row.col.f32.tf32.tf32.f32 "
        "{%0,%1,%2,%3}, {%4,%5,%6,%7}, {%8,%9}, {%0,%1,%2,%3};"
        : "+f"(c[0]), "+f"(c[1]), "+f"(c[2]), "+f"(c[3])
        : "r"(a[0]), "r"(a[1]), "r"(a[2]), "r"(a[3]), "r"(b[0]), "r"(b[1]));
}

__device__ __forceinline__ float gelu_tanh(float v) {
    float x3 = v * v * v;
    float t  = tanhf(0.7978845608028654f * (v + 0.044715f * x3));
    return 0.5f * v * (1.0f + t);
}

// ----------------------------------------------------------------
// prep: tf32-round x into g_x, zero counters
__global__ void prep_kernel(const float* __restrict__ x) {
    int i = blockIdx.x * blockDim.x + threadIdx.x;
    if (i < EE) g_count[i] = 0;
    const int n4 = TT * DD / 4;
    const int stride = gridDim.x * blockDim.x;
    for (int j = i; j < n4; j += stride) {
        float4 v = reinterpret_cast<const float4*>(x)[j];
        uint4 u = { f2tf(v.x), f2tf(v.y), f2tf(v.z), f2tf(v.w) };
        reinterpret_cast<uint4*>(g_x)[j] = u;
    }
}

__global__ void gate_kernel(const float* __restrict__ x,
                            const float* __restrict__ Wg,
                            const float* __restrict__ bg,
                            float* __restrict__ out_idx, int write_idx) {
    int warp = (blockIdx.x * blockDim.x + threadIdx.x) >> 5;
    int lane = threadIdx.x & 31;
    if (warp >= TT) return;
    const float* xr = x + (size_t)warp * DD;

    float acc[EE];
#pragma unroll
    for (int e = 0; e < EE; e++) acc[e] = 0.0f;
    for (int d = lane; d < DD; d += 32) {
        float xv = xr[d];
        const float* wr = Wg + (size_t)d * EE;
#pragma unroll
        for (int e = 0; e < EE; e++) acc[e] += xv * wr[e];
    }
#pragma unroll
    for (int off = 16; off > 0; off >>= 1) {
#pragma unroll
        for (int e = 0; e < EE; e++)
            acc[e] += __shfl_xor_sync(0xFFFFFFFFu, acc[e], off);
    }
    if (lane == 0) {
        float v[EE];
#pragma unroll
        for (int e = 0; e < EE; e++) v[e] = acc[e] + bg[e];
        int e0 = 0;
#pragma unroll
        for (int e = 1; e < EE; e++) if (v[e] > v[e0]) e0 = e;
        int e1 = -1;
#pragma unroll
        for (int e = 0; e < EE; e++)
            if (e != e0 && (e1 < 0 || v[e] > v[e1])) e1 = e;

        float a1 = expf(v[e1] - v[e0]);
        float s  = 1.0f + a1;
        float w0 = 1.0f / s;
        float w1 = a1 / s;

        int p0 = atomicAdd(&g_count[e0], 1);
        g_tok[e0 * TT + p0] = warp;
        int p1 = atomicAdd(&g_count[e1], 1);
        g_tok[e1 * TT + p1] = warp;

        g_se[2 * warp] = e0;  g_sp[2 * warp] = p0;  g_wt2[2 * warp] = w0;
        g_se[2 * warp + 1] = e1;  g_sp[2 * warp + 1] = p1;  g_wt2[2 * warp + 1] = w1;

        if (write_idx) {
            out_idx[warp * 2 + 0] = (float)e0;
            out_idx[warp * 2 + 1] = (float)e1;
        }
    }
}

__global__ void prefix_kernel() {
    if (threadIdx.x == 0) {
        int s = 0;
#pragma unroll
        for (int e = 0; e < EE; e++) { g_offset[e] = s; s += g_count[e]; }
    }
}

// ---------------- HMMA tf32 grouped FFN GEMM ----------------
// SECOND=false: A = g_x gathered rows, B = W1[e] [DD,HH], epi: tf32(gelu(.+b1)) -> g_h
// SECOND=true : A = g_h rows,          B = W2[e] [HH,DD], epi: (.+b2) -> g_y
template <bool SECOND>
__global__ void __launch_bounds__(NTHREADS, 2)
ffn_kernel(const float* __restrict__ W, const float* __restrict__ bias) {
    const int KDIM = SECOND ? HH : DD;
    const int NDIM = SECOND ? DD : HH;
    const int NS   = KDIM / BK;

    const int e   = blockIdx.x >> 4;
    const int mt_ = blockIdx.x & 15;
    const int cnt = g_count[e];
    const int m0  = mt_ * BM;
    if (m0 >= cnt) return;
    const int n0 = blockIdx.y * BN;
    const int gbase = g_offset[e];

    __shared__ int stok[BM];
    extern __shared__ uint32_t smem[];
    uint32_t* const Bsm = smem + STAGES * A_BUF_W;
    const uint32_t sbaseA = smem_u32(smem);
    const uint32_t sbaseB = sbaseA + STAGES * A_BUF_B;

    const int tid  = threadIdx.x;
    const int lane = tid & 31;
    const int wid  = tid >> 5;
    const int wm   = wid & 1;      // 2 warps along M (64 rows each)
    const int wn   = wid >> 1;     // 2 warps along N (64 cols each)
    const int lr   = lane >> 2;    // 0..7
    const int lc   = lane & 3;     // 0..3

    if (!SECOND) {
        if (tid < BM) {
            int r = m0 + tid;
            stok[tid] = (r < cnt) ? g_tok[e * TT + r] : g_tok[e * TT];
        }
        __syncthreads();
    }

    // ---- producer setup ----
    // A: 8 chunks of 16B per thread per slab. chunk i: row = (tid>>3)+16i, k-quad (tid&7)*4
    const char* Agbase = SECOND ? (const char*)g_h : (const char*)g_x;
    uint32_t aoff[8];     // byte offset of row start in source
    uint32_t adst[8];     // SMEM byte addr (stage 0)
#pragma unroll
    for (int i = 0; i < 8; i++) {
        const int row = (tid >> 3) + 16 * i;
        if (SECOND) aoff[i] = (uint32_t)((gbase + m0 + row) * HH * 4);
        else        aoff[i] = (uint32_t)(stok[row] * DD * 4);
        adst[i] = sbaseA + (uint32_t)((row * A_STRIDE + (tid & 7) * 4) * 4);
    }
    const uint32_t akq = (uint32_t)((tid & 7) * 16);   // byte offset within k-slab

    // B: 8 chunks of 16B per thread per slab. chunk i: k = (tid>>5)+4i, 16B-col (tid&31)
    const float* Wb = W + (size_t)e * KDIM * NDIM + n0 + (tid & 31) * 4;
    const int bk0 = tid >> 5;
    const uint32_t bdst0 = sbaseB + (uint32_t)((bk0 * B_STRIDE + (tid & 31) * 4) * 4);

    // ---- consumer setup ----
    // A ldsm lane address: tiles {rows0-7,k0-3},{rows8-15,k0-3},{rows0-7,k4-7},{rows8-15,k4-7}
    const uint32_t a_lane = sbaseA +
        (uint32_t)(((wm * 64 + (lane & 15)) * A_STRIDE + (lane >> 4) * 4) * 4);
    // B frag word base: (lc)*B_STRIDE + wn*64 + lr   (+ n*8, + ks*8*B_STRIDE, b1 at +4*B_STRIDE)
    const int bfrag0 = lc * B_STRIDE + wn * 64 + lr;

    float c[4][8][4];
#pragma unroll
    for (int m = 0; m < 4; m++)
#pragma unroll
        for (int n = 0; n < 8; n++)
#pragma unroll
            for (int j = 0; j < 4; j++) c[m][n][j] = 0.0f;

    // ---- produce stages 0 and 1 ----
#pragma unroll
    for (int st = 0; st < 2; st++) {
        const uint32_t k0b = (uint32_t)(st * BK * 4);
#pragma unroll
        for (int i = 0; i < 8; i++)
            CP_ASYNC16(adst[i] + st * A_BUF_B, Agbase + aoff[i] + k0b + akq);
#pragma unroll
        for (int i = 0; i < 8; i++)
            CP_ASYNC16(bdst0 + st * B_BUF_B + i * (4 * B_STRIDE * 4),
                       (const char*)(Wb + (size_t)(st * BK + bk0 + 4 * i) * NDIM));
        CP_COMMIT();
    }

    // ---- main loop ----
    int buf = 0, pbuf = 2;
    for (int s = 0; s < NS; s++) {
        CP_WAIT(1);
        __syncthreads();

        const uint32_t aAddr = a_lane + buf * A_BUF_B;
        const uint32_t* Bp = Bsm + buf * B_BUF_W + bfrag0;
#pragma unroll
        for (int ks = 0; ks < 4; ks++) {
            uint32_t a[4][4];
#pragma unroll
            for (int m = 0; m < 4; m++)
                ldsm4(a[m], aAddr + m * (16 * A_STRIDE * 4) + ks * 32);
            uint32_t b[8][2];
            const uint32_t* Bk = Bp + ks * 8 * B_STRIDE;
#pragma unroll
            for (int n = 0; n < 8; n++) {
                b[n][0] = f2tf_u(Bk[n * 8]);
                b[n][1] = f2tf_u(Bk[n * 8 + 4 * B_STRIDE]);
            }
#pragma unroll
            for (int m = 0; m < 4; m++)
#pragma unroll
                for (int n = 0; n < 8; n++)
                    mma_tf32(c[m][n], a[m], b[n]);
        }

        if (s + 2 < NS) {
            const uint32_t k0b = (uint32_t)((s + 2) * BK * 4);
            const int kw = (s + 2) * BK;
#pragma unroll
            for (int i = 0; i < 8; i++)
                CP_ASYNC16(adst[i] + pbuf * A_BUF_B, Agbase + aoff[i] + k0b + akq);
#pragma unroll
            for (int i = 0; i < 8; i++)
                CP_ASYNC16(bdst0 + pbuf * B_BUF_B + i * (4 * B_STRIDE * 4),
                           (const char*)(Wb + (size_t)(kw + bk0 + 4 * i) * NDIM));
        }
        CP_COMMIT();   // empty group near tail keeps wait-count uniform

        buf  = (buf == 2) ? 0 : buf + 1;
        pbuf = (pbuf == 2) ? 0 : pbuf + 1;
    }

    // ---- epilogue ----
#pragma unroll
    for (int n = 0; n < 8; n++) {
        const int col = n0 + wn * 64 + n * 8 + 2 * lc;
        const float bv0 = bias[e * NDIM + col];
        const float bv1 = bias[e * NDIM + col + 1];
#pragma unroll
        for (int m = 0; m < 4; m++) {
#pragma unroll
            for (int h = 0; h < 2; h++) {
                const int rloc = wm * 64 + m * 16 + h * 8 + lr;
                const int rg   = m0 + rloc;
                if (rg < cnt) {
                    float v0 = c[m][n][2 * h + 0] + bv0;
                    float v1 = c[m][n][2 * h + 1] + bv1;
                    if (!SECOND) {
                        float2 o = { __uint_as_float(f2tf(gelu_tanh(v0))),
                                     __uint_as_float(f2tf(gelu_tanh(v1))) };
                        *reinterpret_cast<float2*>(&g_h[(size_t)(gbase + rg) * HH + col]) = o;
                    } else {
                        float2 o = { v0, v1 };
                        *reinterpret_cast<float2*>(&g_y[(size_t)(gbase + rg) * DD + col]) = o;
                    }
                }
            }
        }
    }
}

// combine: out[t] = w0*y[slot0] + w1*y[slot1]
__global__ void combine_kernel(float* __restrict__ out) {
    const int t = blockIdx.x;
    __shared__ int   s0, s1;
    __shared__ float w0, w1;
    if (threadIdx.x == 0) {
        s0 = g_offset[g_se[2 * t]]     + g_sp[2 * t];
        s1 = g_offset[g_se[2 * t + 1]] + g_sp[2 * t + 1];
        w0 = g_wt2[2 * t];
        w1 = g_wt2[2 * t + 1];
    }
    __syncthreads();
    const int d = threadIdx.x;
    float4 y0 = reinterpret_cast<const float4*>(g_y + (size_t)s0 * DD)[d];
    float4 y1 = reinterpret_cast<const float4*>(g_y + (size_t)s1 * DD)[d];
    float4 o = { w0 * y0.x + w1 * y1.x, w0 * y0.y + w1 * y1.y,
                 w0 * y0.z + w1 * y1.z, w0 * y0.w + w1 * y1.w };
    reinterpret_cast<float4*>(out + (size_t)t * DD)[d] = o;
}

// ----------------------------------------------------------------
extern "C" void kernel_launch(void* const* d_in, const int* in_sizes, int n_in,
                              void* d_out, int out_size) {
    const float* x  = (const float*)d_in[0];
    const float* Wg = (const float*)d_in[1];
    const float* bg = (const float*)d_in[2];
    const float* W1 = (const float*)d_in[3];
    const float* b1 = (const float*)d_in[4];
    const float* W2 = (const float*)d_in[5];
    const float* b2 = (const float*)d_in[6];
    float* out = (float*)d_out;

    const int write_idx = (out_size >= TT * DD + 2 * TT) ? 1 : 0;
    float* out_idx = out + (size_t)TT * DD;

    static int attr_done = 0;
    if (!attr_done) {
        cudaFuncSetAttribute(ffn_kernel<false>, cudaFuncAttributeMaxDynamicSharedMemorySize, SMEM_DYN);
        cudaFuncSetAttribute(ffn_kernel<true>,  cudaFuncAttributeMaxDynamicSharedMemorySize, SMEM_DYN);
        attr_done = 1;
    }

    prep_kernel<<<512, 256>>>(x);
    gate_kernel<<<(TT * 32 + 255) / 256, 256>>>(x, Wg, bg, out_idx, write_idx);
    prefix_kernel<<<1, 32>>>();

    ffn_kernel<false><<<dim3(EE * 16, HH / BN), NTHREADS, SMEM_DYN>>>(W1, b1);
    ffn_kernel<true ><<<dim3(EE * 16, DD / BN), NTHREADS, SMEM_DYN>>>(W2, b2);

    combine_kernel<<<TT, 256>>>(out);
}

// round 7
// speedup vs baseline: 1.5115x; 1.5115x over previous
#include <cuda_runtime.h>
#include <math.h>
#include <stdint.h>

#define TT 2048
#define DD 1024
#define HH 2048
#define EE 8

#define BM 128
#define BN 128
#define BK 32
#define NT 256

// SMEM word layout per stage: A [128][36], B [32][136]
#define A_STRIDE 36
#define B_STRIDE 136
#define A_BUF_W (BM * A_STRIDE)            // 4608 words
#define B_BUF_W (BK * B_STRIDE)            // 4352 words
#define A_BUF_B (A_BUF_W * 4)
#define B_BUF_B (B_BUF_W * 4)
#define SMEM_DYN (2 * (A_BUF_B + B_BUF_B))   // 71680 B

// -------- device scratch (no runtime allocation allowed) --------
__device__ int   g_count[EE];
__device__ int   g_offset[EE];
__device__ int   g_tok[EE * TT];
__device__ int   g_se[2 * TT];
__device__ int   g_sp[2 * TT];
__device__ float g_wt2[2 * TT];
__device__ __align__(16) float g_x[(size_t)TT * DD];                 // tf32-rounded x
__device__ __align__(16) float g_h[(size_t)(2 * TT + BM) * HH];      // gelu out (tf32-rounded)
__device__ __align__(16) float g_y[(size_t)(2 * TT) * DD];           // per-slot ffn2 out

// ---------------- helpers ----------------
__device__ __forceinline__ uint32_t smem_u32(const void* p) {
    uint32_t a;
    asm("{ .reg .u64 t; cvta.to.shared.u64 t, %1; cvt.u32.u64 %0, t; }" : "=r"(a) : "l"(p));
    return a;
}
__device__ __forceinline__ uint32_t f2tf(float f) {
    uint32_t r;
    asm("cvt.rna.tf32.f32 %0, %1;" : "=r"(r) : "f"(f));
    return r;
}
#define CP_ASYNC16(dst, src) \
    asm volatile("cp.async.cg.shared.global [%0], [%1], 16;" :: "r"(dst), "l"(src) : "memory")
#define CP_COMMIT()  asm volatile("cp.async.commit_group;" ::: "memory")
#define CP_WAIT0()   asm volatile("cp.async.wait_group 0;" ::: "memory")

__device__ __forceinline__ void ldsm4(uint32_t* r, uint32_t addr) {
    asm volatile("ldmatrix.sync.aligned.m8n8.x4.shared.b16 {%0,%1,%2,%3}, [%4];"
        : "=r"(r[0]), "=r"(r[1]), "=r"(r[2]), "=r"(r[3]) : "r"(addr));
}

__device__ __forceinline__ void mma_tf32(float* c, const uint32_t* a, const uint32_t* b) {
    asm volatile(
        "mma.sync.aligned.m16n8k8.row.col.f32.tf32.tf32.f32 "
        "{%0,%1,%2,%3}, {%4,%5,%6,%7}, {%8,%9}, {%0,%1,%2,%3};"
        : "+f"(c[0]), "+f"(c[1]), "+f"(c[2]), "+f"(c[3])
        : "r"(a[0]), "r"(a[1]), "r"(a[2]), "r"(a[3]), "r"(b[0]), "r"(b[1]));
}

__device__ __forceinline__ float gelu_tanh(float v) {
    float x3 = v * v * v;
    float t  = tanhf(0.7978845608028654f * (v + 0.044715f * x3));
    return 0.5f * v * (1.0f + t);
}

// ----------------------------------------------------------------
__global__ void prep_kernel(const float* __restrict__ x) {
    int i = blockIdx.x * blockDim.x + threadIdx.x;
    if (i < EE) g_count[i] = 0;
    const int n4 = TT * DD / 4;
    const int stride = gridDim.x * blockDim.x;
    for (int j = i; j < n4; j += stride) {
        float4 v = reinterpret_cast<const float4*>(x)[j];
        uint4 u = { f2tf(v.x), f2tf(v.y), f2tf(v.z), f2tf(v.w) };
        reinterpret_cast<uint4*>(g_x)[j] = u;
    }
}

__global__ void gate_kernel(const float* __restrict__ x,
                            const float* __restrict__ Wg,
                            const float* __restrict__ bg,
                            float* __restrict__ out_idx, int write_idx) {
    int warp = (blockIdx.x * blockDim.x + threadIdx.x) >> 5;
    int lane = threadIdx.x & 31;
    if (warp >= TT) return;
    const float* xr = x + (size_t)warp * DD;

    float acc[EE];
#pragma unroll
    for (int e = 0; e < EE; e++) acc[e] = 0.0f;
    for (int d = lane; d < DD; d += 32) {
        float xv = xr[d];
        const float* wr = Wg + (size_t)d * EE;
#pragma unroll
        for (int e = 0; e < EE; e++) acc[e] += xv * wr[e];
    }
#pragma unroll
    for (int off = 16; off > 0; off >>= 1) {
#pragma unroll
        for (int e = 0; e < EE; e++)
            acc[e] += __shfl_xor_sync(0xFFFFFFFFu, acc[e], off);
    }
    if (lane == 0) {
        float v[EE];
#pragma unroll
        for (int e = 0; e < EE; e++) v[e] = acc[e] + bg[e];
        int e0 = 0;
#pragma unroll
        for (int e = 1; e < EE; e++) if (v[e] > v[e0]) e0 = e;
        int e1 = -1;
#pragma unroll
        for (int e = 0; e < EE; e++)
            if (e != e0 && (e1 < 0 || v[e] > v[e1])) e1 = e;

        float a1 = expf(v[e1] - v[e0]);
        float s  = 1.0f + a1;
        float w0 = 1.0f / s;
        float w1 = a1 / s;

        int p0 = atomicAdd(&g_count[e0], 1);
        g_tok[e0 * TT + p0] = warp;
        int p1 = atomicAdd(&g_count[e1], 1);
        g_tok[e1 * TT + p1] = warp;

        g_se[2 * warp] = e0;  g_sp[2 * warp] = p0;  g_wt2[2 * warp] = w0;
        g_se[2 * warp + 1] = e1;  g_sp[2 * warp + 1] = p1;  g_wt2[2 * warp + 1] = w1;

        if (write_idx) {
            out_idx[warp * 2 + 0] = (float)e0;
            out_idx[warp * 2 + 1] = (float)e1;
        }
    }
}

__global__ void prefix_kernel() {
    if (threadIdx.x == 0) {
        int s = 0;
#pragma unroll
        for (int e = 0; e < EE; e++) { g_offset[e] = s; s += g_count[e]; }
    }
}

// ---------------- HMMA tf32 grouped FFN GEMM ----------------
// 256 threads = 8 warps (4 along M x 2 along N), warp tile 32x64, 2 CTAs/SM.
// SECOND=false: A = g_x gathered rows, B = W1[e] [DD,HH], epi: tf32(gelu(.+b1)) -> g_h
// SECOND=true : A = g_h rows,          B = W2[e] [HH,DD], epi: (.+b2) -> g_y
template <bool SECOND>
__global__ void __launch_bounds__(NT, 2)
ffn_kernel(const float* __restrict__ W, const float* __restrict__ bias) {
    const int KDIM = SECOND ? HH : DD;
    const int NDIM = SECOND ? DD : HH;
    const int NS   = KDIM / BK;

    const int e   = blockIdx.x >> 4;
    const int mt_ = blockIdx.x & 15;
    const int cnt = g_count[e];
    const int m0  = mt_ * BM;
    if (m0 >= cnt) return;
    const int n0 = blockIdx.y * BN;
    const int gbase = g_offset[e];

    __shared__ int stok[BM];
    extern __shared__ uint32_t smem[];
    uint32_t* const Bsm = smem + 2 * A_BUF_W;     // [2][32][136]
    const uint32_t sbaseA = smem_u32(smem);

    const int tid  = threadIdx.x;
    const int lane = tid & 31;
    const int wid  = tid >> 5;
    const int wm   = wid & 3;      // 4 warps along M (32 rows each)
    const int wn   = wid >> 2;     // 2 warps along N (64 cols each)
    const int lr   = lane >> 2;    // 0..7
    const int lc   = lane & 3;     // 0..3

    if (!SECOND) {
        if (tid < BM) {
            int r = m0 + tid;
            stok[tid] = (r < cnt) ? g_tok[e * TT + r] : g_tok[e * TT];
        }
        __syncthreads();
    }

    // ---- A producer: 4 chunks of 16B per thread per slab ----
    // chunk i: row = (tid>>3) + 32*i, k-quad (tid&7)*4
    const char* Agbase = SECOND ? (const char*)g_h : (const char*)g_x;
    uint32_t aoff[4];     // source row byte offset
    uint32_t adst[4];     // SMEM byte addr (stage 0)
#pragma unroll
    for (int i = 0; i < 4; i++) {
        const int row = (tid >> 3) + 32 * i;
        if (SECOND) aoff[i] = (uint32_t)((gbase + m0 + row) * HH * 4);
        else        aoff[i] = (uint32_t)(stok[row] * DD * 4);
        adst[i] = sbaseA + (uint32_t)((row * A_STRIDE + (tid & 7) * 4) * 4);
    }
    const uint32_t akq = (uint32_t)((tid & 7) * 16);

    // ---- B producer: 4 float4 per thread per slab ----
    // chunk i: k = (tid>>5) + 8*i, n-quad (tid&31)*4
    const float* Wb = W + (size_t)e * KDIM * NDIM + n0 + (tid & 31) * 4;
    const int bk0 = tid >> 5;                          // 0..7
    const int bw0 = bk0 * B_STRIDE + (tid & 31) * 4;   // word offset in B buf

    // ---- consumer setup ----
    const uint32_t a_lane = sbaseA +
        (uint32_t)(((wm * 32 + (lane & 15)) * A_STRIDE + (lane >> 4) * 4) * 4);
    const int bfrag0 = lc * B_STRIDE + wn * 64 + lr;

    float c[2][8][4];
#pragma unroll
    for (int m = 0; m < 2; m++)
#pragma unroll
        for (int n = 0; n < 8; n++)
#pragma unroll
            for (int j = 0; j < 4; j++) c[m][n][j] = 0.0f;

    // ---- prologue: slab 0 ----
#pragma unroll
    for (int i = 0; i < 4; i++)
        CP_ASYNC16(adst[i], Agbase + aoff[i] + akq);
    CP_COMMIT();
    {
        float4 pb[4];
#pragma unroll
        for (int i = 0; i < 4; i++)
            pb[i] = *reinterpret_cast<const float4*>(Wb + (size_t)(bk0 + 8 * i) * NDIM);
#pragma unroll
        for (int i = 0; i < 4; i++) {
            uint4 u = { f2tf(pb[i].x), f2tf(pb[i].y), f2tf(pb[i].z), f2tf(pb[i].w) };
            *reinterpret_cast<uint4*>(&Bsm[bw0 + i * 8 * B_STRIDE]) = u;
        }
    }
    CP_WAIT0();
    __syncthreads();

    // ---- main loop (2-stage) ----
    for (int s = 0; s < NS; s++) {
        const int buf = s & 1;
        const int nb  = buf ^ 1;
        float4 pb[4];
        if (s + 1 < NS) {
            const uint32_t k0b = (uint32_t)((s + 1) * BK * 4);
#pragma unroll
            for (int i = 0; i < 4; i++)
                CP_ASYNC16(adst[i] + nb * A_BUF_B, Agbase + aoff[i] + k0b + akq);
            CP_COMMIT();
            const int kw = (s + 1) * BK;
#pragma unroll
            for (int i = 0; i < 4; i++)
                pb[i] = *reinterpret_cast<const float4*>(Wb + (size_t)(kw + bk0 + 8 * i) * NDIM);
        }

        const uint32_t aAddr = a_lane + buf * A_BUF_B;
        const uint32_t* Bp = Bsm + buf * B_BUF_W + bfrag0;
#pragma unroll
        for (int ks = 0; ks < 4; ks++) {
            uint32_t a[2][4];
#pragma unroll
            for (int m = 0; m < 2; m++)
                ldsm4(a[m], aAddr + m * (16 * A_STRIDE * 4) + ks * 32);
            uint32_t b[8][2];
            const uint32_t* Bk = Bp + ks * 8 * B_STRIDE;
#pragma unroll
            for (int n = 0; n < 8; n++) {
                b[n][0] = Bk[n * 8];
                b[n][1] = Bk[n * 8 + 4 * B_STRIDE];
            }
#pragma unroll
            for (int m = 0; m < 2; m++)
#pragma unroll
                for (int n = 0; n < 8; n++)
                    mma_tf32(c[m][n], a[m], b[n]);
        }

        if (s + 1 < NS) {
            uint32_t* Bw = Bsm + nb * B_BUF_W;
#pragma unroll
            for (int i = 0; i < 4; i++) {
                uint4 u = { f2tf(pb[i].x), f2tf(pb[i].y), f2tf(pb[i].z), f2tf(pb[i].w) };
                *reinterpret_cast<uint4*>(&Bw[bw0 + i * 8 * B_STRIDE]) = u;
            }
            CP_WAIT0();
            __syncthreads();
        }
    }

    // ---- epilogue ----
#pragma unroll
    for (int n = 0; n < 8; n++) {
        const int col = n0 + wn * 64 + n * 8 + 2 * lc;
        const float bv0 = bias[e * NDIM + col];
        const float bv1 = bias[e * NDIM + col + 1];
#pragma unroll
        for (int m = 0; m < 2; m++) {
#pragma unroll
            for (int h = 0; h < 2; h++) {
                const int rloc = wm * 32 + m * 16 + h * 8 + lr;
                const int rg   = m0 + rloc;
                if (rg < cnt) {
                    float v0 = c[m][n][2 * h + 0] + bv0;
                    float v1 = c[m][n][2 * h + 1] + bv1;
                    if (!SECOND) {
                        float2 o = { __uint_as_float(f2tf(gelu_tanh(v0))),
                                     __uint_as_float(f2tf(gelu_tanh(v1))) };
                        *reinterpret_cast<float2*>(&g_h[(size_t)(gbase + rg) * HH + col]) = o;
                    } else {
                        float2 o = { v0, v1 };
                        *reinterpret_cast<float2*>(&g_y[(size_t)(gbase + rg) * DD + col]) = o;
                    }
                }
            }
        }
    }
}

// combine: out[t] = w0*y[slot0] + w1*y[slot1]
__global__ void combine_kernel(float* __restrict__ out) {
    const int t = blockIdx.x;
    __shared__ int   s0, s1;
    __shared__ float w0, w1;
    if (threadIdx.x == 0) {
        s0 = g_offset[g_se[2 * t]]     + g_sp[2 * t];
        s1 = g_offset[g_se[2 * t + 1]] + g_sp[2 * t + 1];
        w0 = g_wt2[2 * t];
        w1 = g_wt2[2 * t + 1];
    }
    __syncthreads();
    const int d = threadIdx.x;
    float4 y0 = reinterpret_cast<const float4*>(g_y + (size_t)s0 * DD)[d];
    float4 y1 = reinterpret_cast<const float4*>(g_y + (size_t)s1 * DD)[d];
    float4 o = { w0 * y0.x + w1 * y1.x, w0 * y0.y + w1 * y1.y,
                 w0 * y0.z + w1 * y1.z, w0 * y0.w + w1 * y1.w };
    reinterpret_cast<float4*>(out + (size_t)t * DD)[d] = o;
}

// ----------------------------------------------------------------
extern "C" void kernel_launch(void* const* d_in, const int* in_sizes, int n_in,
                              void* d_out, int out_size) {
    const float* x  = (const float*)d_in[0];
    const float* Wg = (const float*)d_in[1];
    const float* bg = (const float*)d_in[2];
    const float* W1 = (const float*)d_in[3];
    const float* b1 = (const float*)d_in[4];
    const float* W2 = (const float*)d_in[5];
    const float* b2 = (const float*)d_in[6];
    float* out = (float*)d_out;

    const int write_idx = (out_size >= TT * DD + 2 * TT) ? 1 : 0;
    float* out_idx = out + (size_t)TT * DD;

    static int attr_done = 0;
    if (!attr_done) {
        cudaFuncSetAttribute(ffn_kernel<false>, cudaFuncAttributeMaxDynamicSharedMemorySize, SMEM_DYN);
        cudaFuncSetAttribute(ffn_kernel<true>,  cudaFuncAttributeMaxDynamicSharedMemorySize, SMEM_DYN);
        attr_done = 1;
    }

    prep_kernel<<<512, 256>>>(x);
    gate_kernel<<<(TT * 32 + 255) / 256, 256>>>(x, Wg, bg, out_idx, write_idx);
    prefix_kernel<<<1, 32>>>();

    ffn_kernel<false><<<dim3(EE * 16, HH / BN), NT, SMEM_DYN>>>(W1, b1);
    ffn_kernel<true ><<<dim3(EE * 16, DD / BN), NT, SMEM_DYN>>>(W2, b2);

    combine_kernel<<<TT, 256>>>(out);
}

// round 8
// speedup vs baseline: 1.5279x; 1.0108x over previous
#include <cuda_runtime.h>
#include <math.h>
#include <stdint.h>

#define TT 2048
#define DD 1024
#define HH 2048
#define EE 8

#define BM 128
#define BN 128
#define BK 32
#define NT 256

// SMEM word layout: A 3 stages of [128][36], B 2 stages of [32][136]
#define A_STRIDE 36
#define B_STRIDE 136
#define A_BUF_W (BM * A_STRIDE)            // 4608 words
#define B_BUF_W (BK * B_STRIDE)            // 4352 words
#define A_BUF_B (A_BUF_W * 4)
#define B_BUF_B (B_BUF_W * 4)
#define SMEM_DYN (3 * A_BUF_B + 2 * B_BUF_B)   // 90112 B

// -------- device scratch (no runtime allocation allowed) --------
__device__ int   g_count[EE];
__device__ int   g_offset[EE];
__device__ int   g_tok[EE * TT];
__device__ int   g_se[2 * TT];
__device__ int   g_sp[2 * TT];
__device__ float g_wt2[2 * TT];
__device__ __align__(16) float g_x[(size_t)TT * DD];                 // tf32-rounded x
__device__ __align__(16) float g_h[(size_t)(2 * TT + BM) * HH];      // gelu out (tf32-rounded)
__device__ __align__(16) float g_y[(size_t)(2 * TT) * DD];           // per-slot ffn2 out

// ---------------- helpers ----------------
__device__ __forceinline__ uint32_t smem_u32(const void* p) {
    uint32_t a;
    asm("{ .reg .u64 t; cvta.to.shared.u64 t, %1; cvt.u32.u64 %0, t; }" : "=r"(a) : "l"(p));
    return a;
}
__device__ __forceinline__ uint32_t f2tf(float f) {
    uint32_t r;
    asm("cvt.rna.tf32.f32 %0, %1;" : "=r"(r) : "f"(f));
    return r;
}
#define CP_ASYNC16(dst, src) \
    asm volatile("cp.async.cg.shared.global [%0], [%1], 16;" :: "r"(dst), "l"(src) : "memory")
#define CP_COMMIT()  asm volatile("cp.async.commit_group;" ::: "memory")
#define CP_WAIT(n)   asm volatile("cp.async.wait_group %0;" :: "n"(n) : "memory")

__device__ __forceinline__ void ldsm4(uint32_t* r, uint32_t addr) {
    asm volatile("ldmatrix.sync.aligned.m8n8.x4.shared.b16 {%0,%1,%2,%3}, [%4];"
        : "=r"(r[0]), "=r"(r[1]), "=r"(r[2]), "=r"(r[3]) : "r"(addr));
}

__device__ __forceinline__ void mma_tf32(float* c, const uint32_t* a, const uint32_t* b) {
    asm volatile(
        "mma.sync.aligned.m16n8k8.row.col.f32.tf32.tf32.f32 "
        "{%0,%1,%2,%3}, {%4,%5,%6,%7}, {%8,%9}, {%0,%1,%2,%3};"
        : "+f"(c[0]), "+f"(c[1]), "+f"(c[2]), "+f"(c[3])
        : "r"(a[0]), "r"(a[1]), "r"(a[2]), "r"(a[3]), "r"(b[0]), "r"(b[1]));
}

__device__ __forceinline__ float gelu_tanh(float v) {
    float x3 = v * v * v;
    float t  = tanhf(0.7978845608028654f * (v + 0.044715f * x3));
    return 0.5f * v * (1.0f + t);
}

// ----------------------------------------------------------------
__global__ void prep_kernel(const float* __restrict__ x) {
    int i = blockIdx.x * blockDim.x + threadIdx.x;
    if (i < EE) g_count[i] = 0;
    const int n4 = TT * DD / 4;
    const int stride = gridDim.x * blockDim.x;
    for (int j = i; j < n4; j += stride) {
        float4 v = reinterpret_cast<const float4*>(x)[j];
        uint4 u = { f2tf(v.x), f2tf(v.y), f2tf(v.z), f2tf(v.w) };
        reinterpret_cast<uint4*>(g_x)[j] = u;
    }
}

__global__ void gate_kernel(const float* __restrict__ x,
                            const float* __restrict__ Wg,
                            const float* __restrict__ bg,
                            float* __restrict__ out_idx, int write_idx) {
    int warp = (blockIdx.x * blockDim.x + threadIdx.x) >> 5;
    int lane = threadIdx.x & 31;
    if (warp >= TT) return;
    const float* xr = x + (size_t)warp * DD;

    float acc[EE];
#pragma unroll
    for (int e = 0; e < EE; e++) acc[e] = 0.0f;
    for (int d = lane; d < DD; d += 32) {
        float xv = xr[d];
        const float* wr = Wg + (size_t)d * EE;
#pragma unroll
        for (int e = 0; e < EE; e++) acc[e] += xv * wr[e];
    }
#pragma unroll
    for (int off = 16; off > 0; off >>= 1) {
#pragma unroll
        for (int e = 0; e < EE; e++)
            acc[e] += __shfl_xor_sync(0xFFFFFFFFu, acc[e], off);
    }
    if (lane == 0) {
        float v[EE];
#pragma unroll
        for (int e = 0; e < EE; e++) v[e] = acc[e] + bg[e];
        int e0 = 0;
#pragma unroll
        for (int e = 1; e < EE; e++) if (v[e] > v[e0]) e0 = e;
        int e1 = -1;
#pragma unroll
        for (int e = 0; e < EE; e++)
            if (e != e0 && (e1 < 0 || v[e] > v[e1])) e1 = e;

        float a1 = expf(v[e1] - v[e0]);
        float s  = 1.0f + a1;
        float w0 = 1.0f / s;
        float w1 = a1 / s;

        int p0 = atomicAdd(&g_count[e0], 1);
        g_tok[e0 * TT + p0] = warp;
        int p1 = atomicAdd(&g_count[e1], 1);
        g_tok[e1 * TT + p1] = warp;

        g_se[2 * warp] = e0;  g_sp[2 * warp] = p0;  g_wt2[2 * warp] = w0;
        g_se[2 * warp + 1] = e1;  g_sp[2 * warp + 1] = p1;  g_wt2[2 * warp + 1] = w1;

        if (write_idx) {
            out_idx[warp * 2 + 0] = (float)e0;
            out_idx[warp * 2 + 1] = (float)e1;
        }
    }
}

__global__ void prefix_kernel() {
    if (threadIdx.x == 0) {
        int s = 0;
#pragma unroll
        for (int e = 0; e < EE; e++) { g_offset[e] = s; s += g_count[e]; }
    }
}

// ---------------- HMMA tf32 grouped FFN GEMM ----------------
// 256 threads = 8 warps (4 along M x 2 along N), warp tile 32x64, 2 CTAs/SM.
// A pipeline: 3-stage cp.async ring, distance-2 prefetch, wait_group(1).
// B pipeline: LDG->reg->cvt->STS, 2-stage.
template <bool SECOND>
__global__ void __launch_bounds__(NT, 2)
ffn_kernel(const float* __restrict__ W, const float* __restrict__ bias) {
    const int KDIM = SECOND ? HH : DD;
    const int NDIM = SECOND ? DD : HH;
    const int NS   = KDIM / BK;

    const int e   = blockIdx.x >> 4;
    const int mt_ = blockIdx.x & 15;
    const int cnt = g_count[e];
    const int m0  = mt_ * BM;
    if (m0 >= cnt) return;
    const int n0 = blockIdx.y * BN;
    const int gbase = g_offset[e];

    __shared__ int stok[BM];
    extern __shared__ uint32_t smem[];
    uint32_t* const Bsm = smem + 3 * A_BUF_W;     // [2][32][136]
    const uint32_t sbaseA = smem_u32(smem);

    const int tid  = threadIdx.x;
    const int lane = tid & 31;
    const int wid  = tid >> 5;
    const int wm   = wid & 3;      // 4 warps along M (32 rows each)
    const int wn   = wid >> 2;     // 2 warps along N (64 cols each)
    const int lr   = lane >> 2;    // 0..7
    const int lc   = lane & 3;     // 0..3

    if (!SECOND) {
        if (tid < BM) {
            int r = m0 + tid;
            stok[tid] = (r < cnt) ? g_tok[e * TT + r] : g_tok[e * TT];
        }
        __syncthreads();
    }

    // ---- A producer: 4 chunks of 16B per thread per slab ----
    const char* Agbase = SECOND ? (const char*)g_h : (const char*)g_x;
    uint32_t aoff[4];
    uint32_t adst[4];
#pragma unroll
    for (int i = 0; i < 4; i++) {
        const int row = (tid >> 3) + 32 * i;
        if (SECOND) aoff[i] = (uint32_t)((gbase + m0 + row) * HH * 4);
        else        aoff[i] = (uint32_t)(stok[row] * DD * 4);
        adst[i] = sbaseA + (uint32_t)((row * A_STRIDE + (tid & 7) * 4) * 4);
    }
    const uint32_t akq = (uint32_t)((tid & 7) * 16);

    // ---- B producer: 4 float4 per thread per slab ----
    const float* Wb = W + (size_t)e * KDIM * NDIM + n0 + (tid & 31) * 4;
    const int bk0 = tid >> 5;
    const int bw0 = bk0 * B_STRIDE + (tid & 31) * 4;

    // ---- consumer setup ----
    const uint32_t a_lane = sbaseA +
        (uint32_t)(((wm * 32 + (lane & 15)) * A_STRIDE + (lane >> 4) * 4) * 4);
    const int bfrag0 = lc * B_STRIDE + wn * 64 + lr;

    float c[2][8][4];
#pragma unroll
    for (int m = 0; m < 2; m++)
#pragma unroll
        for (int n = 0; n < 8; n++)
#pragma unroll
            for (int j = 0; j < 4; j++) c[m][n][j] = 0.0f;

    // ---- prologue: commit A groups for slabs 0 and 1; B slab 0 via regs ----
#pragma unroll
    for (int st = 0; st < 2; st++) {
        const uint32_t k0b = (uint32_t)(st * BK * 4);
#pragma unroll
        for (int i = 0; i < 4; i++)
            CP_ASYNC16(adst[i] + (uint32_t)(st * A_BUF_B), Agbase + aoff[i] + k0b + akq);
        CP_COMMIT();
    }
    {
        float4 pb[4];
#pragma unroll
        for (int i = 0; i < 4; i++)
            pb[i] = *reinterpret_cast<const float4*>(Wb + (size_t)(bk0 + 8 * i) * NDIM);
#pragma unroll
        for (int i = 0; i < 4; i++) {
            uint4 u = { f2tf(pb[i].x), f2tf(pb[i].y), f2tf(pb[i].z), f2tf(pb[i].w) };
            *reinterpret_cast<uint4*>(&Bsm[bw0 + i * 8 * B_STRIDE]) = u;
        }
    }
    CP_WAIT(1);          // A slab 0 landed; slab 1 may still fly
    __syncthreads();

    // ---- main loop ----
    uint32_t caOff = 0;                       // consume A stage byte offset (0,1,2)*A_BUF_B
    uint32_t paOff = 2 * A_BUF_B;             // prefetch A stage byte offset
    for (int s = 0; s < NS; s++) {
        // prefetch A slab s+2 into stage (s+2)%3 ; uniform one commit per iter
        if (s + 2 < NS) {
            const uint32_t k0b = (uint32_t)((s + 2) * BK * 4);
#pragma unroll
            for (int i = 0; i < 4; i++)
                CP_ASYNC16(adst[i] + paOff, Agbase + aoff[i] + k0b + akq);
        }
        CP_COMMIT();

        // prefetch B slab s+1 into registers
        float4 pb[4];
        if (s + 1 < NS) {
            const int kw = (s + 1) * BK;
#pragma unroll
            for (int i = 0; i < 4; i++)
                pb[i] = *reinterpret_cast<const float4*>(Wb + (size_t)(kw + bk0 + 8 * i) * NDIM);
        }

        // compute slab s
        const uint32_t aAddr = a_lane + caOff;
        const uint32_t* Bp = Bsm + (s & 1) * B_BUF_W + bfrag0;
#pragma unroll
        for (int ks = 0; ks < 4; ks++) {
            uint32_t a[2][4];
#pragma unroll
            for (int m = 0; m < 2; m++)
                ldsm4(a[m], aAddr + m * (16 * A_STRIDE * 4) + ks * 32);
            uint32_t b[8][2];
            const uint32_t* Bk = Bp + ks * 8 * B_STRIDE;
#pragma unroll
            for (int n = 0; n < 8; n++) {
                b[n][0] = Bk[n * 8];
                b[n][1] = Bk[n * 8 + 4 * B_STRIDE];
            }
#pragma unroll
            for (int m = 0; m < 2; m++)
#pragma unroll
                for (int n = 0; n < 8; n++)
                    mma_tf32(c[m][n], a[m], b[n]);
        }

        if (s + 1 < NS) {
            uint32_t* Bw = Bsm + ((s + 1) & 1) * B_BUF_W;
#pragma unroll
            for (int i = 0; i < 4; i++) {
                uint4 u = { f2tf(pb[i].x), f2tf(pb[i].y), f2tf(pb[i].z), f2tf(pb[i].w) };
                *reinterpret_cast<uint4*>(&Bw[bw0 + i * 8 * B_STRIDE]) = u;
            }
            CP_WAIT(1);      // slab s+1's A complete; slab s+2's group may fly
            __syncthreads();
        }

        caOff = (caOff == 2 * A_BUF_B) ? 0 : caOff + A_BUF_B;
        paOff = (paOff == 2 * A_BUF_B) ? 0 : paOff + A_BUF_B;
    }

    // ---- epilogue ----
#pragma unroll
    for (int n = 0; n < 8; n++) {
        const int col = n0 + wn * 64 + n * 8 + 2 * lc;
        const float bv0 = bias[e * NDIM + col];
        const float bv1 = bias[e * NDIM + col + 1];
#pragma unroll
        for (int m = 0; m < 2; m++) {
#pragma unroll
            for (int h = 0; h < 2; h++) {
                const int rloc = wm * 32 + m * 16 + h * 8 + lr;
                const int rg   = m0 + rloc;
                if (rg < cnt) {
                    float v0 = c[m][n][2 * h + 0] + bv0;
                    float v1 = c[m][n][2 * h + 1] + bv1;
                    if (!SECOND) {
                        float2 o = { __uint_as_float(f2tf(gelu_tanh(v0))),
                                     __uint_as_float(f2tf(gelu_tanh(v1))) };
                        *reinterpret_cast<float2*>(&g_h[(size_t)(gbase + rg) * HH + col]) = o;
                    } else {
                        float2 o = { v0, v1 };
                        *reinterpret_cast<float2*>(&g_y[(size_t)(gbase + rg) * DD + col]) = o;
                    }
                }
            }
        }
    }
}

// combine: out[t] = w0*y[slot0] + w1*y[slot1]
__global__ void combine_kernel(float* __restrict__ out) {
    const int t = blockIdx.x;
    __shared__ int   s0, s1;
    __shared__ float w0, w1;
    if (threadIdx.x == 0) {
        s0 = g_offset[g_se[2 * t]]     + g_sp[2 * t];
        s1 = g_offset[g_se[2 * t + 1]] + g_sp[2 * t + 1];
        w0 = g_wt2[2 * t];
        w1 = g_wt2[2 * t + 1];
    }
    __syncthreads();
    const int d = threadIdx.x;
    float4 y0 = reinterpret_cast<const float4*>(g_y + (size_t)s0 * DD)[d];
    float4 y1 = reinterpret_cast<const float4*>(g_y + (size_t)s1 * DD)[d];
    float4 o = { w0 * y0.x + w1 * y1.x, w0 * y0.y + w1 * y1.y,
                 w0 * y0.z + w1 * y1.z, w0 * y0.w + w1 * y1.w };
    reinterpret_cast<float4*>(out + (size_t)t * DD)[d] = o;
}

// ----------------------------------------------------------------
extern "C" void kernel_launch(void* const* d_in, const int* in_sizes, int n_in,
                              void* d_out, int out_size) {
    const float* x  = (const float*)d_in[0];
    const float* Wg = (const float*)d_in[1];
    const float* bg = (const float*)d_in[2];
    const float* W1 = (const float*)d_in[3];
    const float* b1 = (const float*)d_in[4];
    const float* W2 = (const float*)d_in[5];
    const float* b2 = (const float*)d_in[6];
    float* out = (float*)d_out;

    const int write_idx = (out_size >= TT * DD + 2 * TT) ? 1 : 0;
    float* out_idx = out + (size_t)TT * DD;

    static int attr_done = 0;
    if (!attr_done) {
        cudaFuncSetAttribute(ffn_kernel<false>, cudaFuncAttributeMaxDynamicSharedMemorySize, SMEM_DYN);
        cudaFuncSetAttribute(ffn_kernel<true>,  cudaFuncAttributeMaxDynamicSharedMemorySize, SMEM_DYN);
        attr_done = 1;
    }

    prep_kernel<<<512, 256>>>(x);
    gate_kernel<<<(TT * 32 + 255) / 256, 256>>>(x, Wg, bg, out_idx, write_idx);
    prefix_kernel<<<1, 32>>>();

    ffn_kernel<false><<<dim3(EE * 16, HH / BN), NT, SMEM_DYN>>>(W1, b1);
    ffn_kernel<true ><<<dim3(EE * 16, DD / BN), NT, SMEM_DYN>>>(W2, b2);

    combine_kernel<<<TT, 256>>>(out);
}